// round 16
// baseline (speedup 1.0000x reference)
#include <cuda_runtime.h>
#include <math.h>

// Problem constants
#define NB 64
#define NF 36
#define NQ 100
#define NT 20
#define NC 92
#define NQUERY (NB * NF * NQ)          // 230400
#define NINST  (NB * NF)               // 2304
#define COST_ELEMS (NQUERY * NT)       // 4608000
#define IDX_ELEMS  (NINST * NT)        // 46080
#define FULLW 0xffffffffu

// ---------------------------------------------------------------------------
// Fused kernel. Block = one (b,f) instance, 128 threads.
//   Pass 1 (half-warp-per-row, coalesced): each 16-lane half loads its row's
//          23 float4 (~4 lines/row), exps in registers, captures label exps
//          via per-lane REGISTER masks (loop-invariant; 0-3 bits/lane) into
//          sbuf[q*21+t], reduces sum -> srs[q] = 1/sum.
//   Pass 2 (thread-per-query, all 32 lanes): R11 box math; prob from sbuf,
//          cost overwrites sbuf in place.
//   Store: coalesced cost store from sbuf.
//   Phase B: warps 1-3 exit; warp 0 runs the R3 auction on -sbuf.
// ---------------------------------------------------------------------------
__global__ __launch_bounds__(128) void fused_kernel(
        const float* __restrict__ logits,
        const float* __restrict__ pboxes,
        const int*   __restrict__ tlabels,
        const float* __restrict__ tboxes,
        float* __restrict__ cost,
        float* __restrict__ out_pred,
        float* __restrict__ out_tgt)
{
    const int inst = blockIdx.x;          // b*36 + f
    const int b = inst / NF;
    const int f = inst - b * NF;
    const int tid  = threadIdx.x;
    const int lane = tid & 31;
    const int warp = tid >> 5;

    __shared__ float    sbuf[NQ * 21];    // exp stash -> cost values (8.4 KB)
    __shared__ float    srs[NQ];          // 1/sum_exp per query
    __shared__ float4   stbc[NT];         // target cxcywh
    __shared__ float4   stbx[NT];         // target xyxy
    __shared__ float    starea[NT];
    __shared__ int      slab[NT];
    __shared__ int      scmp[NT];         // label component within its float4
    __shared__ unsigned tmask[23];        // targets whose label is in float4 i
    __shared__ float    wmx[4], wmn[4];
    // auction state
    __shared__ float    price[NQ];
    __shared__ int      owner[NQ];
    __shared__ int      obj_of[NT];
    __shared__ float    sbid[NT];
    __shared__ int      sobj[NT];
    __shared__ int      blist[NT];

    if (tid < NT) {
        const size_t tb_ = (size_t)(f * NB + b) * NT + tid;
        const float4 tb = ((const float4*)tboxes)[tb_];
        stbc[tid] = tb;
        const float x0 = tb.x - 0.5f * tb.z, y0 = tb.y - 0.5f * tb.w;
        const float x1 = tb.x + 0.5f * tb.z, y1 = tb.y + 0.5f * tb.w;
        stbx[tid]  = make_float4(x0, y0, x1, y1);
        starea[tid] = (x1 - x0) * (y1 - y0);
        const int lab = tlabels[tb_];
        slab[tid] = lab;
        scmp[tid] = lab & 3;
        obj_of[tid] = -1;
    }
    if (tid < 23) tmask[tid] = 0u;
    for (int i = tid; i < NQ; i += 128) { price[i] = 0.0f; owner[i] = -1; }
    __syncthreads();

    if (tid == 0) {
        unsigned m[23];
        #pragma unroll
        for (int i = 0; i < 23; ++i) m[i] = 0u;
        #pragma unroll
        for (int t = 0; t < NT; ++t) m[slab[t] >> 2] |= (1u << t);
        #pragma unroll
        for (int i = 0; i < 23; ++i) tmask[i] = m[i];
    }
    __syncthreads();

    const float* lbase = logits + ((size_t)b * (NF * NQ) + f * NQ) * NC;

    // --- Pass 1: coalesced sum + in-register label capture ---
    {
        const int half = lane >> 4;       // 0 or 1
        const int hl   = lane & 15;
        const unsigned cap_a = tmask[hl];                       // loop-invariant
        const unsigned cap_b = (hl < 7) ? tmask[hl + 16] : 0u;  // register masks

        for (int k = warp; k < NQ / 2; k += 4) {
            const int row = 2 * k + half;
            const float4* r4 = (const float4*)(lbase + (size_t)row * NC);

            const float4 va = r4[hl];
            const float ea0 = __expf(va.x), ea1 = __expf(va.y);
            const float ea2 = __expf(va.z), ea3 = __expf(va.w);
            float s = (ea0 + ea1) + (ea2 + ea3);

            float eb0 = 0.f, eb1 = 0.f, eb2 = 0.f, eb3 = 0.f;
            if (hl < 7) {
                const float4 vb = r4[hl + 16];
                eb0 = __expf(vb.x); eb1 = __expf(vb.y);
                eb2 = __expf(vb.z); eb3 = __expf(vb.w);
                s += (eb0 + eb1) + (eb2 + eb3);
            }

            // per-lane capture (0-3 bits per mask, register-resident)
            unsigned m = cap_a;
            while (m) {
                const int t = __ffs(m) - 1;
                m &= m - 1u;
                const int cm = scmp[t];
                const float ev = (cm == 0) ? ea0 : (cm == 1) ? ea1
                               : (cm == 2) ? ea2 : ea3;
                sbuf[row * 21 + t] = ev;
            }
            m = cap_b;
            while (m) {
                const int t = __ffs(m) - 1;
                m &= m - 1u;
                const int cm = scmp[t];
                const float ev = (cm == 0) ? eb0 : (cm == 1) ? eb1
                               : (cm == 2) ? eb2 : eb3;
                sbuf[row * 21 + t] = ev;
            }

            // intra-half sum reduction (stays within the 16-lane half)
            #pragma unroll
            for (int o = 8; o > 0; o >>= 1) s += __shfl_xor_sync(FULLW, s, o);
            if (hl == 0) srs[row] = __fdividef(1.0f, s);
        }
    }
    __syncthreads();

    // --- Pass 2: thread-per-query box math (R11 body) ---
    float mx = -INFINITY, mn = INFINITY;
    const int q = tid;
    if (q < NQ) {
        const float rs = srs[q];

        const float4 pb = *(const float4*)(pboxes
                          + ((size_t)b * (NF * NQ) + f * NQ + q) * 4);
        const float px0 = pb.x - 0.5f * pb.z;
        const float py0 = pb.y - 0.5f * pb.w;
        const float px1 = pb.x + 0.5f * pb.z;
        const float py1 = pb.y + 0.5f * pb.w;
        const float area1 = (px1 - px0) * (py1 - py0);

        #pragma unroll
        for (int t = 0; t < NT; ++t) {
            const float prob = sbuf[q * 21 + t] * rs;

            const float4 tc = stbc[t];
            const float l1 = fabsf(pb.x - tc.x) + fabsf(pb.y - tc.y)
                           + fabsf(pb.z - tc.z) + fabsf(pb.w - tc.w);

            const float4 tx = stbx[t];
            const float ltx = fmaxf(px0, tx.x), lty = fmaxf(py0, tx.y);
            const float rbx = fminf(px1, tx.z), rby = fminf(py1, tx.w);
            const float iw = fmaxf(rbx - ltx, 0.0f), ih = fmaxf(rby - lty, 0.0f);
            const float inter = iw * ih;
            const float uni = area1 + starea[t] - inter;

            const float elx = fminf(px0, tx.x), ely = fminf(py0, tx.y);
            const float erx = fmaxf(px1, tx.z), ery = fmaxf(py1, tx.w);
            const float ew = fmaxf(erx - elx, 0.0f), eh = fmaxf(ery - ely, 0.0f);
            const float areae = ew * eh;

            const float giou = __fdividef(inter * areae - uni * (areae - uni),
                                          uni * areae);

            const float cv = -prob + 5.0f * l1 - 2.0f * giou;
            sbuf[q * 21 + t] = cv;        // overwrite stash with cost
            const float bv = -cv;
            mx = fmaxf(mx, bv);
            mn = fminf(mn, bv);
        }
    }
    #pragma unroll
    for (int o = 16; o > 0; o >>= 1) {
        mx = fmaxf(mx, __shfl_xor_sync(FULLW, mx, o));
        mn = fminf(mn, __shfl_xor_sync(FULLW, mn, o));
    }
    if (lane == 0) { wmx[warp] = mx; wmn[warp] = mn; }
    __syncthreads();

    // --- coalesced cost store ---
    float* cbase = cost + (size_t)inst * (NQ * NT);
    #pragma unroll 4
    for (int i = tid; i < NQ * NT; i += 128) {
        const int q2 = i / NT, t2 = i - q2 * NT;
        cbase[i] = sbuf[q2 * 21 + t2];
    }

    if (warp != 0) return;

    // =======================================================================
    // Phase B: R3 auction on warp 0; benefit = -sbuf[q*21+t]. (R11 verbatim)
    // =======================================================================
    const int t = lane;
    const float gmx = fmaxf(fmaxf(wmx[0], wmx[1]), fmaxf(wmx[2], wmx[3]));
    const float gmn = fminf(fminf(wmn[0], wmn[1]), fminf(wmn[2], wmn[3]));
    const float eps = (gmx - gmn + 1e-06f) / 1000.0f;
    __syncwarp();

    for (int it = 0; it < 20000; ++it) {
        const bool un = (t < NT) && (obj_of[t] < 0);
        const unsigned mask = __ballot_sync(FULLW, un);
        if (!mask) break;
        const int u = __popc(mask);

        if (un) blist[__popc(mask & ((1u << t) - 1u))] = t;
        __syncwarp();

        const int gp = 32 / u;
        const int gsize = 1 << (31 - __clz(gp));
        const int grp = t / gsize;
        const int lig = t - grp * gsize;
        const bool live = (grp < u);
        const int t2 = blist[live ? grp : 0];

        float b1 = -INFINITY, b2 = -INFINITY;
        int i1 = 0;
        for (int qq = lig; qq < NQ; qq += gsize) {
            const float v = -sbuf[qq * 21 + t2] - price[qq];
            if (v > b1) { b2 = b1; b1 = v; i1 = qq; }
            else if (v > b2) { b2 = v; }
        }
        for (int o = gsize >> 1; o > 0; o >>= 1) {
            const float ob1 = __shfl_xor_sync(FULLW, b1, o);
            const int   oi1 = __shfl_xor_sync(FULLW, i1, o);
            const float ob2 = __shfl_xor_sync(FULLW, b2, o);
            const bool aw = (b1 > ob1) || (b1 == ob1 && i1 < oi1);
            const float lose = aw ? ob1 : b1;
            b2 = fmaxf(lose, fmaxf(b2, ob2));
            b1 = aw ? b1 : ob1;
            i1 = aw ? i1 : oi1;
        }
        if (live && lig == 0) {
            sbid[t2] = price[i1] + (b1 - b2) + eps;
            sobj[t2] = i1;
        }
        __syncwarp();

        bool winf = false;
        int myq = -1;
        if (un) {
            myq = sobj[t];
            const float mybid = sbid[t];
            winf = true;
            for (unsigned mm = mask & ~(1u << t); mm; mm &= mm - 1u) {
                const int t3 = __ffs(mm) - 1;
                if (sobj[t3] == myq) {
                    const float ob = sbid[t3];
                    if (ob > mybid || (ob == mybid && t3 < t)) winf = false;
                }
            }
        }
        __syncwarp();

        int old = -1;
        if (winf) old = owner[myq];
        __syncwarp();
        if (winf && old >= 0) obj_of[old] = -1;   // evictions first
        __syncwarp();
        if (winf) {
            obj_of[t] = myq;
            price[myq] = sbid[t];
            owner[myq] = t;
        }
        __syncwarp();
    }

    // stable argsort of obj_of
    if (t < NT) {
        const int v = obj_of[t];
        int rank = 0;
        #pragma unroll
        for (int t3 = 0; t3 < NT; ++t3) {
            const int v2 = obj_of[t3];
            rank += (v2 < v) || (v2 == v && t3 < t);
        }
        out_pred[(size_t)inst * NT + rank] = (float)v;
        out_tgt [(size_t)inst * NT + rank] = (float)t;
    }
}

// ---------------------------------------------------------------------------
extern "C" void kernel_launch(void* const* d_in, const int* in_sizes, int n_in,
                              void* d_out, int out_size)
{
    const float* logits  = (const float*)d_in[0];  // (64, 3600, 92)
    const float* pboxes  = (const float*)d_in[1];  // (64, 3600, 4)
    const int*   tlabels = (const int*)  d_in[2];  // (36, 64, 20)
    const float* tboxes  = (const float*)d_in[3];  // (36, 64, 20, 4)

    float* out  = (float*)d_out;
    float* cost = out;
    float* pidx = out + COST_ELEMS;
    float* tidx = out + COST_ELEMS + IDX_ELEMS;

    fused_kernel<<<NINST, 128>>>(logits, pboxes, tlabels, tboxes,
                                 cost, pidx, tidx);
}

// round 17
// speedup vs baseline: 1.2376x; 1.2376x over previous
#include <cuda_runtime.h>
#include <math.h>

// Problem constants
#define NB 64
#define NF 36
#define NQ 100
#define NT 20
#define NC 92
#define NQUERY (NB * NF * NQ)          // 230400
#define NINST  (NB * NF)               // 2304
#define COST_ELEMS (NQUERY * NT)       // 4608000
#define IDX_ELEMS  (NINST * NT)        // 46080
#define FULLW 0xffffffffu

// ---------------------------------------------------------------------------
// Fused kernel (R11 base). Block = one (b,f) instance, 128 threads.
//   Phase A: R11 cost body (per-thread row reads) -> sbuf (stride 21).
//   Store:   warps 1-3 store cost to gmem and exit; warp 0 starts auction
//            immediately.
//   Phase B: warp 0 runs the R3 auction on -sbuf, with a u==1 fast path
//            (single bidder wins unconditionally; no staging/resolution).
// ---------------------------------------------------------------------------
__global__ __launch_bounds__(128) void fused_kernel(
        const float* __restrict__ logits,
        const float* __restrict__ pboxes,
        const int*   __restrict__ tlabels,
        const float* __restrict__ tboxes,
        float* __restrict__ cost,
        float* __restrict__ out_pred,
        float* __restrict__ out_tgt)
{
    const int inst = blockIdx.x;          // b*36 + f
    const int b = inst / NF;
    const int f = inst - b * NF;
    const int tid  = threadIdx.x;
    const int lane = tid & 31;
    const int warp = tid >> 5;

    __shared__ float  sbuf[NQ * 21];      // cost values, stride 21 (8.4 KB)
    __shared__ float4 stbc[NT];           // target cxcywh
    __shared__ float4 stbx[NT];           // target xyxy
    __shared__ float  sarea[NT];
    __shared__ int    slab[NT];
    __shared__ float  wmx[4], wmn[4];
    // auction state
    __shared__ float  price[NQ];
    __shared__ int    owner[NQ];
    __shared__ int    obj_of[NT];
    __shared__ float  sbid[NT];
    __shared__ int    sobj[NT];
    __shared__ int    blist[NT];

    if (tid < NT) {
        const size_t tb_ = (size_t)(f * NB + b) * NT + tid;
        const float4 tb = ((const float4*)tboxes)[tb_];
        stbc[tid] = tb;
        const float x0 = tb.x - 0.5f * tb.z, y0 = tb.y - 0.5f * tb.w;
        const float x1 = tb.x + 0.5f * tb.z, y1 = tb.y + 0.5f * tb.w;
        stbx[tid]  = make_float4(x0, y0, x1, y1);
        sarea[tid] = (x1 - x0) * (y1 - y0);
        slab[tid]  = tlabels[tb_];
        obj_of[tid] = -1;
    }
    for (int i = tid; i < NQ; i += 128) { price[i] = 0.0f; owner[i] = -1; }
    __syncthreads();

    // --- Phase A: R11 cost body ---
    float mx = -INFINITY, mn = INFINITY;
    const int q = tid;
    if (q < NQ) {
        const float* row = logits + ((size_t)b * (NF * NQ) + f * NQ + q) * NC;
        const float4* r4 = (const float4*)row;

        float s = 0.0f;
        #pragma unroll
        for (int i = 0; i < 23; ++i) {
            const float4 v = r4[i];
            s += (__expf(v.x) + __expf(v.y)) + (__expf(v.z) + __expf(v.w));
        }
        const float rs = __fdividef(1.0f, s);

        const float4 pb = *(const float4*)(pboxes + ((size_t)b * (NF * NQ) + f * NQ + q) * 4);
        const float px0 = pb.x - 0.5f * pb.z;
        const float py0 = pb.y - 0.5f * pb.w;
        const float px1 = pb.x + 0.5f * pb.z;
        const float py1 = pb.y + 0.5f * pb.w;
        const float area1 = (px1 - px0) * (py1 - py0);

        #pragma unroll
        for (int t = 0; t < NT; ++t) {
            const float prob = __expf(__ldg(row + slab[t])) * rs;   // L1 hit

            const float4 tc = stbc[t];
            const float l1 = fabsf(pb.x - tc.x) + fabsf(pb.y - tc.y)
                           + fabsf(pb.z - tc.z) + fabsf(pb.w - tc.w);

            const float4 tx = stbx[t];
            const float ltx = fmaxf(px0, tx.x), lty = fmaxf(py0, tx.y);
            const float rbx = fminf(px1, tx.z), rby = fminf(py1, tx.w);
            const float iw = fmaxf(rbx - ltx, 0.0f), ih = fmaxf(rby - lty, 0.0f);
            const float inter = iw * ih;
            const float uni = area1 + sarea[t] - inter;

            const float elx = fminf(px0, tx.x), ely = fminf(py0, tx.y);
            const float erx = fmaxf(px1, tx.z), ery = fmaxf(py1, tx.w);
            const float ew = fmaxf(erx - elx, 0.0f), eh = fmaxf(ery - ely, 0.0f);
            const float areae = ew * eh;

            const float giou = __fdividef(inter * areae - uni * (areae - uni),
                                          uni * areae);

            const float cv = -prob + 5.0f * l1 - 2.0f * giou;
            sbuf[q * 21 + t] = cv;
            const float bv = -cv;                 // benefit
            mx = fmaxf(mx, bv);
            mn = fminf(mn, bv);
        }
    }
    #pragma unroll
    for (int o = 16; o > 0; o >>= 1) {
        mx = fmaxf(mx, __shfl_xor_sync(FULLW, mx, o));
        mn = fminf(mn, __shfl_xor_sync(FULLW, mn, o));
    }
    if (lane == 0) { wmx[warp] = mx; wmn[warp] = mn; }
    __syncthreads();

    // --- warps 1-3: cost store (overlaps warp 0's auction), then exit ---
    if (warp != 0) {
        float* cbase = cost + (size_t)inst * (NQ * NT);
        #pragma unroll 4
        for (int i = tid - 32; i < NQ * NT; i += 96) {
            const int q2 = i / NT, t2 = i - q2 * NT;
            cbase[i] = sbuf[q2 * 21 + t2];
        }
        return;
    }

    // =======================================================================
    // Phase B: R3 auction on warp 0; benefit = -sbuf[q*21+t].
    // =======================================================================
    const int t = lane;
    const float gmx = fmaxf(fmaxf(wmx[0], wmx[1]), fmaxf(wmx[2], wmx[3]));
    const float gmn = fminf(fminf(wmn[0], wmn[1]), fminf(wmn[2], wmn[3]));
    const float eps = (gmx - gmn + 1e-06f) / 1000.0f;
    __syncwarp();

    for (int it = 0; it < 20000; ++it) {
        const bool un = (t < NT) && (obj_of[t] < 0);
        const unsigned mask = __ballot_sync(FULLW, un);
        if (!mask) break;
        const int u = __popc(mask);

        if (u == 1) {
            // ---- fast path: single bidder t0 always wins ----
            const int t0 = __ffs(mask) - 1;
            float b1 = -INFINITY, b2 = -INFINITY;
            int i1 = 0;
            for (int qq = lane; qq < NQ; qq += 32) {
                const float v = -sbuf[qq * 21 + t0] - price[qq];
                if (v > b1) { b2 = b1; b1 = v; i1 = qq; }
                else if (v > b2) { b2 = v; }
            }
            #pragma unroll
            for (int o = 16; o > 0; o >>= 1) {
                const float ob1 = __shfl_xor_sync(FULLW, b1, o);
                const int   oi1 = __shfl_xor_sync(FULLW, i1, o);
                const float ob2 = __shfl_xor_sync(FULLW, b2, o);
                const bool aw = (b1 > ob1) || (b1 == ob1 && i1 < oi1);
                const float lose = aw ? ob1 : b1;
                b2 = fmaxf(lose, fmaxf(b2, ob2));
                b1 = aw ? b1 : ob1;
                i1 = aw ? i1 : oi1;
            }
            if (lane == t0) {
                const float bid = price[i1] + (b1 - b2) + eps;
                const int old = owner[i1];
                if (old >= 0) obj_of[old] = -1;
                obj_of[t0] = i1;
                price[i1] = bid;
                owner[i1] = t0;
            }
            __syncwarp();
            continue;
        }

        // ---- general path (R3 verbatim) ----
        if (un) blist[__popc(mask & ((1u << t) - 1u))] = t;
        __syncwarp();

        const int gp = 32 / u;
        const int gsize = 1 << (31 - __clz(gp));
        const int grp = t / gsize;
        const int lig = t - grp * gsize;
        const bool live = (grp < u);
        const int t2 = blist[live ? grp : 0];

        float b1 = -INFINITY, b2 = -INFINITY;
        int i1 = 0;
        for (int qq = lig; qq < NQ; qq += gsize) {
            const float v = -sbuf[qq * 21 + t2] - price[qq];
            if (v > b1) { b2 = b1; b1 = v; i1 = qq; }
            else if (v > b2) { b2 = v; }
        }
        for (int o = gsize >> 1; o > 0; o >>= 1) {
            const float ob1 = __shfl_xor_sync(FULLW, b1, o);
            const int   oi1 = __shfl_xor_sync(FULLW, i1, o);
            const float ob2 = __shfl_xor_sync(FULLW, b2, o);
            const bool aw = (b1 > ob1) || (b1 == ob1 && i1 < oi1);
            const float lose = aw ? ob1 : b1;
            b2 = fmaxf(lose, fmaxf(b2, ob2));
            b1 = aw ? b1 : ob1;
            i1 = aw ? i1 : oi1;
        }
        if (live && lig == 0) {
            sbid[t2] = price[i1] + (b1 - b2) + eps;
            sobj[t2] = i1;
        }
        __syncwarp();

        bool winf = false;
        int myq = -1;
        if (un) {
            myq = sobj[t];
            const float mybid = sbid[t];
            winf = true;
            for (unsigned mm = mask & ~(1u << t); mm; mm &= mm - 1u) {
                const int t3 = __ffs(mm) - 1;
                if (sobj[t3] == myq) {
                    const float ob = sbid[t3];
                    if (ob > mybid || (ob == mybid && t3 < t)) winf = false;
                }
            }
        }
        __syncwarp();

        int old = -1;
        if (winf) old = owner[myq];
        __syncwarp();
        if (winf && old >= 0) obj_of[old] = -1;   // evictions first
        __syncwarp();
        if (winf) {
            obj_of[t] = myq;
            price[myq] = sbid[t];
            owner[myq] = t;
        }
        __syncwarp();
    }

    // stable argsort of obj_of
    if (t < NT) {
        const int v = obj_of[t];
        int rank = 0;
        #pragma unroll
        for (int t3 = 0; t3 < NT; ++t3) {
            const int v2 = obj_of[t3];
            rank += (v2 < v) || (v2 == v && t3 < t);
        }
        out_pred[(size_t)inst * NT + rank] = (float)v;
        out_tgt [(size_t)inst * NT + rank] = (float)t;
    }
}

// ---------------------------------------------------------------------------
extern "C" void kernel_launch(void* const* d_in, const int* in_sizes, int n_in,
                              void* d_out, int out_size)
{
    const float* logits  = (const float*)d_in[0];  // (64, 3600, 92)
    const float* pboxes  = (const float*)d_in[1];  // (64, 3600, 4)
    const int*   tlabels = (const int*)  d_in[2];  // (36, 64, 20)
    const float* tboxes  = (const float*)d_in[3];  // (36, 64, 20, 4)

    float* out  = (float*)d_out;
    float* cost = out;
    float* pidx = out + COST_ELEMS;
    float* tidx = out + COST_ELEMS + IDX_ELEMS;

    fused_kernel<<<NINST, 128>>>(logits, pboxes, tlabels, tboxes,
                                 cost, pidx, tidx);
}